// round 15
// baseline (speedup 1.0000x reference)
#include <cuda_runtime.h>
#include <cuda_bf16.h>
#include <math.h>
#include <stdint.h>

#define BATCH 2048
#define NIN   512
#define NOUT  1024
#define LAMBD 0.2f
#define ADMM_ITERS 100
#define NEWTON_ITERS 7
#define NCTAS 128

// ---------------- scratch (static __device__ globals: allocation-free) ----------------
__device__ __align__(16) float g_w   [NOUT*NIN];
__device__ __align__(16) float g_wT  [NIN*NOUT];
__device__ __align__(16) float g_S   [NIN*NIN];
__device__ __align__(16) float g_Xa  [NIN*NIN];
__device__ __align__(16) float g_Xb  [NIN*NIN];
__device__ __align__(16) float g_Yn  [NIN*NIN];
__device__ __align__(16) float g_T   [NOUT*NIN];
__device__ __align__(16) float g_Minv[NOUT*NOUT];
__device__ __align__(16) float g_Atb [BATCH*NOUT];
// packed tile-major buffers: [tile][chunk] blocks of 128x64 bf16 (16KB), swizzle baked in
__device__ __align__(16) __nv_bfloat16 g_Mh [NOUT*NOUT];
__device__ __align__(16) __nv_bfloat16 g_Ml [NOUT*NOUT];
__device__ __align__(16) __nv_bfloat16 g_R0h[BATCH*NOUT];
__device__ __align__(16) __nv_bfloat16 g_R0l[BATCH*NOUT];
__device__ __align__(16) __nv_bfloat16 g_R1h[BATCH*NOUT];
__device__ __align__(16) __nv_bfloat16 g_R1l[BATCH*NOUT];
__device__ float g_pv0[NIN];
__device__ float g_alpha;
__device__ int   g_sync;

// ---------------- PTX helpers ----------------
__device__ __forceinline__ uint32_t smem_u32(const void* p) {
    uint32_t a;
    asm("{ .reg .u64 t; cvta.to.shared.u64 t, %1; cvt.u32.u64 %0, t; }" : "=r"(a) : "l"(p));
    return a;
}
__device__ __forceinline__ void cpbulk(uint32_t dst, const void* src, uint32_t bytes, uint32_t mbar) {
    asm volatile(
        "cp.async.bulk.shared::cta.global.mbarrier::complete_tx::bytes [%0], [%1], %2, [%3];"
        :: "r"(dst), "l"(src), "r"(bytes), "r"(mbar) : "memory");
}
#define FENCE_ASYNC()    asm volatile("fence.proxy.async.shared::cta;" ::: "memory")
#define MBAR_INIT(mb, c) asm volatile("mbarrier.init.shared.b64 [%0], %1;" :: "r"(mb), "r"(c) : "memory")
#define MBAR_INVAL(mb)   asm volatile("mbarrier.inval.shared.b64 [%0];" :: "r"(mb) : "memory")
#define MBAR_EXPECT_TX(mb, n) asm volatile("mbarrier.arrive.expect_tx.shared.b64 _, [%0], %1;" :: "r"(mb), "r"(n) : "memory")
#define MBAR_ARRIVE(mb) asm volatile("mbarrier.arrive.shared.b64 _, [%0];" :: "r"(mb) : "memory")
#define MBAR_WAIT(mb, ph) do {                                                  \
    uint32_t _m = (mb), _p = (ph), _d;                                          \
    asm volatile("{\n\t.reg .pred p;\n\t"                                       \
        "mbarrier.try_wait.parity.acquire.cta.shared::cta.b64 p, [%1], %2;\n\t" \
        "selp.b32 %0, 1, 0, p;\n\t}" : "=r"(_d) : "r"(_m), "r"(_p) : "memory"); \
    if (!_d) {                                                                  \
        asm volatile("{\n\t.reg .pred P1;\n\t"                                  \
            "WL_%=:\n\t"                                                        \
            "mbarrier.try_wait.parity.acquire.cta.shared::cta.b64 P1, [%0], %1, 0x989680;\n\t" \
            "@P1 bra.uni WD_%=;\n\t"                                            \
            "bra.uni WL_%=;\n\t"                                                \
            "WD_%=:\n\t}" :: "r"(_m), "r"(_p) : "memory");                      \
    }                                                                           \
} while (0)
__device__ __forceinline__ void ldsm4(uint32_t* r, uint32_t addr) {
    asm volatile("ldmatrix.sync.aligned.m8n8.x4.shared.b16 {%0,%1,%2,%3}, [%4];"
        : "=r"(r[0]), "=r"(r[1]), "=r"(r[2]), "=r"(r[3]) : "r"(addr));
}
__device__ __forceinline__ void mma_bf16(float* c, const uint32_t* a, const uint32_t* b) {
    asm volatile(
        "mma.sync.aligned.m16n8k16.row.col.f32.bf16.bf16.f32 "
        "{%0,%1,%2,%3}, {%4,%5,%6,%7}, {%8,%9}, {%0,%1,%2,%3};"
        : "+f"(c[0]), "+f"(c[1]), "+f"(c[2]), "+f"(c[3])
        : "r"(a[0]), "r"(a[1]), "r"(a[2]), "r"(a[3]), "r"(b[0]), "r"(b[1]));
}

// packed offset (elements): matrix [rows][1024], tile = 128 rows x 64 cols, swizzle baked
__device__ __forceinline__ int packed_off(int row, int col) {
    const int r = row & 127;
    return ((row >> 7) * 16 + (col >> 6)) * 8192
         + r * 64 + ((((col & 63) >> 3) ^ (r & 7)) * 8) + (col & 7);
}

// ---------------- small kernels ----------------
__global__ void norm_rows_kernel(const float* __restrict__ win) {
    const int row = blockIdx.x;
    __shared__ float red[256];
    float s = 0.f;
    for (int c = threadIdx.x; c < NIN; c += 256) {
        float v = win[row * NIN + c];
        s += v * v;
    }
    red[threadIdx.x] = s;
    __syncthreads();
    for (int st = 128; st > 0; st >>= 1) {
        if (threadIdx.x < st) red[threadIdx.x] += red[threadIdx.x + st];
        __syncthreads();
    }
    const float inv = 1.f / sqrtf(red[0]);
    for (int c = threadIdx.x; c < NIN; c += 256)
        g_w[row * NIN + c] = win[row * NIN + c] * inv;
}

__global__ void transpose_kernel() {
    __shared__ float t[32][33];
    const int bx = blockIdx.x * 32, by = blockIdx.y * 32;
    for (int j = 0; j < 32; j += 8)
        t[threadIdx.y + j][threadIdx.x] = g_w[(by + threadIdx.y + j) * NIN + bx + threadIdx.x];
    __syncthreads();
    for (int j = 0; j < 32; j += 8)
        g_wT[(bx + threadIdx.y + j) * NOUT + by + threadIdx.x] = t[threadIdx.x][threadIdx.y + j];
}

__global__ void power_v0_kernel() {
    const int i = threadIdx.x;
    g_pv0[i] = 1.0f + 0.1f * (float)(i % 7);
}

__global__ void power_mv_kernel(const float* __restrict__ x, float* __restrict__ y) {
    const int row = blockIdx.x;
    __shared__ float red[128];
    float s = 0.f;
    for (int c = threadIdx.x; c < NIN; c += 128) s += g_S[row * NIN + c] * x[c];
    red[threadIdx.x] = s;
    __syncthreads();
    for (int st = 64; st > 0; st >>= 1) {
        if (threadIdx.x < st) red[threadIdx.x] += red[threadIdx.x + st];
        __syncthreads();
    }
    if (threadIdx.x == 0) y[row] = red[0];
}

__global__ void alpha_kernel(const float* __restrict__ v2, const float* __restrict__ v3) {
    __shared__ float r2[512], r3[512];
    const int i = threadIdx.x;
    r2[i] = v2[i] * v2[i];
    r3[i] = v3[i] * v3[i];
    __syncthreads();
    for (int st = 256; st > 0; st >>= 1) {
        if (i < st) { r2[i] += r2[i + st]; r3[i] += r3[i + st]; }
        __syncthreads();
    }
    if (i == 0) g_alpha = 2.f / (1.f + 1.2f * sqrtf(r3[0] / r2[0]));
}

__global__ void init_x0_kernel() {
    const int i = blockIdx.x * blockDim.x + threadIdx.x;
    if (i < NIN * NIN) {
        int r = i / NIN, c = i % NIN;
        g_Xa[i] = (r == c) ? g_alpha : 0.f;
    }
}

__global__ void split_minv_kernel() {
    const int i = blockIdx.x * blockDim.x + threadIdx.x;
    const int n = i >> 10, k = i & 1023;
    float v = g_Minv[i];
    __nv_bfloat16 h = __float2bfloat16(v);
    const int off = packed_off(n, k);
    g_Mh[off] = h;
    g_Ml[off] = __float2bfloat16(v - __bfloat162float(h));
}

__global__ void init_state_kernel() {   // R0 = packed split(Atb); reset global barrier
    const int i = blockIdx.x * blockDim.x + threadIdx.x;
    const int m = i >> 10, k = i & 1023;
    float v = g_Atb[i];
    __nv_bfloat16 h = __float2bfloat16(v);
    const int off = packed_off(m, k);
    g_R0h[off] = h;
    g_R0l[off] = __float2bfloat16(v - __bfloat162float(h));
    if (i == 0) g_sync = 0;
}

// ---------------- SIMT GEMM (prologue) ----------------
enum { EPI_PLAIN = 0, EPI_ADD_EYE = 1, EPI_EYE_MINUS = 2, EPI_2EYE_MINUS = 3 };

template <int BM, int BN, int TM, int TN, int EPI, int TB>
__global__ __launch_bounds__((BM / TM) * (BN / TN))
void gemm_k(const float* __restrict__ A, const float* __restrict__ B,
            float* __restrict__ C, int M, int N, int K)
{
    constexpr int BK = 16;
    constexpr int THREADS = (BM / TM) * (BN / TN);
    __shared__ float As[BK][BM];
    __shared__ float Bs[BK][BN];
    const int bm = blockIdx.y * BM, bn = blockIdx.x * BN;
    const int tid = threadIdx.x;
    const int tr = (tid / (BN / TN)) * TM;
    const int tc = (tid % (BN / TN)) * TN;

    float acc[TM][TN];
#pragma unroll
    for (int i = 0; i < TM; i++)
#pragma unroll
        for (int j = 0; j < TN; j++) acc[i][j] = 0.f;

    const float* Ap = A + (size_t)bm * K;
    constexpr int SLOTS_A = BM * (BK / 4);

    for (int k0 = 0; k0 < K; k0 += BK) {
        for (int s = tid; s < SLOTS_A; s += THREADS) {
            int r = s / (BK / 4), lc = (s % (BK / 4)) * 4;
            float4 v = *(const float4*)(Ap + (size_t)r * K + k0 + lc);
            As[lc + 0][r] = v.x; As[lc + 1][r] = v.y;
            As[lc + 2][r] = v.z; As[lc + 3][r] = v.w;
        }
        if (TB == 0) {
            constexpr int SLOTS_B = BN * (BK / 4);
            const float* Bp = B + (size_t)bn * K;
            for (int s = tid; s < SLOTS_B; s += THREADS) {
                int r = s / (BK / 4), lc = (s % (BK / 4)) * 4;
                float4 v = *(const float4*)(Bp + (size_t)r * K + k0 + lc);
                Bs[lc + 0][r] = v.x; Bs[lc + 1][r] = v.y;
                Bs[lc + 2][r] = v.z; Bs[lc + 3][r] = v.w;
            }
        } else {
            constexpr int SLOTS_B = BK * (BN / 4);
            for (int s = tid; s < SLOTS_B; s += THREADS) {
                int kk = s / (BN / 4), c4 = (s % (BN / 4)) * 4;
                float4 v = *(const float4*)(B + (size_t)(k0 + kk) * N + bn + c4);
                *(float4*)&Bs[kk][c4] = v;
            }
        }
        __syncthreads();
#pragma unroll
        for (int k = 0; k < BK; k++) {
            float a[TM], b[TN];
#pragma unroll
            for (int v = 0; v < TM; v += 4) *(float4*)&a[v] = *(const float4*)&As[k][tr + v];
#pragma unroll
            for (int v = 0; v < TN; v += 4) *(float4*)&b[v] = *(const float4*)&Bs[k][tc + v];
#pragma unroll
            for (int i = 0; i < TM; i++)
#pragma unroll
                for (int j = 0; j < TN; j++) acc[i][j] = fmaf(a[i], b[j], acc[i][j]);
        }
        __syncthreads();
    }

#pragma unroll
    for (int i = 0; i < TM; i++) {
        const int row = bm + tr + i;
#pragma unroll
        for (int j0 = 0; j0 < TN; j0 += 4) {
            const int col = bn + tc + j0;
            const size_t idx = (size_t)row * N + col;
            float r[4] = {acc[i][j0], acc[i][j0 + 1], acc[i][j0 + 2], acc[i][j0 + 3]};
            if (EPI == EPI_PLAIN) {
                *(float4*)(C + idx) = make_float4(r[0], r[1], r[2], r[3]);
            } else {
                float o[4];
#pragma unroll
                for (int c = 0; c < 4; c++) {
                    float e = (row == col + c) ? 1.f : 0.f;
                    o[c] = (EPI == EPI_ADD_EYE)  ? (r[c] + e)
                         : (EPI == EPI_EYE_MINUS) ? (e - r[c])
                                                  : (2.f * e - r[c]);
                }
                *(float4*)(C + idx) = make_float4(o[0], o[1], o[2], o[3]);
            }
        }
    }
}

// ---------------- persistent ADMM v2: B-prefetch overlaps the global barrier ----------------
// fullA/fullB split per stage: B (constant Minv) fills issue BEFORE the global
// barrier wait; A fills after. Global barrier: arrive at end of iteration,
// wait at top of the next. Epilogue vectorized (uint4 R stores, float4 Atb).
// Per-element ADMM arithmetic identical to R14 => rel_err canary 6.88588e-05.
#define KC     64
#define NCH    (NOUT / KC)              // 16
#define TILE_B (128 * 64 * 2)           // 16384 bytes
#define STG_B  (4 * TILE_B)             // 65536 per stage
#define NSTAGE 2
#define SM_U    (NSTAGE * STG_B)        // 131072
#define SM_MBAR (SM_U + 65536)          // 196608
#define SM_TOT  (SM_MBAR + 64)          // 196672
#define LDS_STAGE 132                   // fp32 epilogue stage row stride (67584 <= 131072 ring)

__global__ __launch_bounds__(1024, 1)
void admm_persistent_kernel(float* __restrict__ V)
{
    extern __shared__ char smem[];
    const uint32_t sb = smem_u32(smem);
    const int tid = threadIdx.x;
    const int wid = tid >> 5, lane = tid & 31;
    const int g = lane >> 2, t4 = lane & 3;
    const int warp_m = wid & 3;
    const int warp_n = wid >> 2;
    const int bm = blockIdx.y * 128, bn = blockIdx.x * 128;
    const int mt16 = blockIdx.y * 16, nt16 = blockIdx.x * 16;

    const int lq = lane >> 3, lr = lane & 7;
    const int a_row0 = warp_m * 32 + (lq & 1) * 8 + lr;
    const int a_kq   = lq >> 1;
    const int b_row0 = warp_n * 16 + (lq >> 1) * 8 + lr;
    const int b_kq   = lq & 1;

    const uint32_t fullA_mb = sb + SM_MBAR;        // 2 x 8
    const uint32_t fullB_mb = sb + SM_MBAR + 16;   // 2 x 8
    const uint32_t empty_mb = sb + SM_MBAR + 32;   // 2 x 8
    float* Usm = (float*)(smem + SM_U);

#pragma unroll
    for (int i = 0; i < 16; i++) Usm[tid + i * 1024] = 0.f;
    __syncthreads();

    for (int it = 0; it < ADMM_ITERS; it++) {
        // (re)initialize pipeline barriers: phase 0 every iteration
        if (tid == 0) {
#pragma unroll
            for (int s = 0; s < NSTAGE; s++) {
                if (it > 0) {
                    MBAR_INVAL(fullA_mb + s * 8); MBAR_INVAL(fullB_mb + s * 8);
                    MBAR_INVAL(empty_mb + s * 8);
                }
                MBAR_INIT(fullA_mb + s * 8, 1);
                MBAR_INIT(fullB_mb + s * 8, 1);
                MBAR_INIT(empty_mb + s * 8, 32);
            }
        }
        FENCE_ASYNC();     // order prior generic smem stores before async bulk writes
        __syncthreads();

        auto fillB = [&](int ch) {
            const int s = ch & 1;
            const uint32_t mb = fullB_mb + s * 8;
            MBAR_EXPECT_TX(mb, (uint32_t)(2 * TILE_B));
            const uint32_t base = sb + s * STG_B;
            cpbulk(base + 2 * TILE_B, g_Mh + (size_t)(nt16 + ch) * 8192, TILE_B, mb);
            cpbulk(base + 3 * TILE_B, g_Ml + (size_t)(nt16 + ch) * 8192, TILE_B, mb);
        };
        auto fillA = [&](int ch) {
            const __nv_bfloat16* Ah = (it & 1) ? g_R1h : g_R0h;
            const __nv_bfloat16* Al = (it & 1) ? g_R1l : g_R0l;
            const int s = ch & 1;
            const uint32_t mb = fullA_mb + s * 8;
            MBAR_EXPECT_TX(mb, (uint32_t)(2 * TILE_B));
            const uint32_t base = sb + s * STG_B;
            cpbulk(base,          Ah + (size_t)(mt16 + ch) * 8192, TILE_B, mb);
            cpbulk(base + TILE_B, Al + (size_t)(mt16 + ch) * 8192, TILE_B, mb);
        };

        // B (constant) prefetch BEFORE the global barrier wait
        if (tid == 0) { fillB(0); fillB(1); }

        // wait for all CTAs to finish the previous iteration (R writes visible)
        if (it > 0) {
            if (tid == 0) {
                const int target = NCTAS * it;
                while (atomicAdd(&g_sync, 0) < target) { }
                __threadfence();
                fillA(0); fillA(1);
            }
        } else {
            if (tid == 0) { fillA(0); fillA(1); }
        }

        float acc[2][2][4];
#pragma unroll
        for (int i = 0; i < 2; i++)
#pragma unroll
            for (int j = 0; j < 2; j++)
#pragma unroll
                for (int c = 0; c < 4; c++) acc[i][j][c] = 0.f;

        for (int ch = 0; ch < NCH; ch++) {
            const int s = ch & 1;
            const int ph = (ch >> 1) & 1;
            MBAR_WAIT(fullB_mb + s * 8, ph);
            MBAR_WAIT(fullA_mb + s * 8, ph);

            const uint32_t tAh = sb + s * STG_B;
            const uint32_t tAl = tAh + TILE_B;
            const uint32_t tBh = tAh + 2 * TILE_B;
            const uint32_t tBl = tAh + 3 * TILE_B;

#pragma unroll
            for (int ks = 0; ks < KC / 16; ks++) {
                const int kb8 = ks * 2;
                uint32_t ah[2][4], al[2][4], bh[4], bl[4];
#pragma unroll
                for (int mi = 0; mi < 2; mi++) {
                    const int row = a_row0 + mi * 16;
                    const uint32_t off = row * 128 + (((kb8 + a_kq) ^ (row & 7)) * 16);
                    ldsm4(ah[mi], tAh + off);
                    ldsm4(al[mi], tAl + off);
                }
                {
                    const uint32_t off = b_row0 * 128 + (((kb8 + b_kq) ^ (b_row0 & 7)) * 16);
                    ldsm4(bh, tBh + off);
                    ldsm4(bl, tBl + off);
                }
                if (ks == 3 && lane == 0 && ch < NCH - 2) MBAR_ARRIVE(empty_mb + s * 8);
                // product-outermost: per-acc order hh, hl, lh (canary order)
#pragma unroll
                for (int mi = 0; mi < 2; mi++) {
                    mma_bf16(acc[mi][0], ah[mi], bh);
                    mma_bf16(acc[mi][1], ah[mi], bh + 2);
                }
#pragma unroll
                for (int mi = 0; mi < 2; mi++) {
                    mma_bf16(acc[mi][0], ah[mi], bl);
                    mma_bf16(acc[mi][1], ah[mi], bl + 2);
                }
#pragma unroll
                for (int mi = 0; mi < 2; mi++) {
                    mma_bf16(acc[mi][0], al[mi], bh);
                    mma_bf16(acc[mi][1], al[mi], bh + 2);
                }
            }
            if (tid == 0 && ch + 2 < NCH) {
                MBAR_WAIT(empty_mb + s * 8, (ch >> 1) & 1);   // per-iter phase from 0
                fillB(ch + 2);
                fillA(ch + 2);
            }
        }

        __syncthreads();   // mainloop done; ring smem reusable for staging

        // stage accumulators -> smem (fp32, stride LDS_STAGE at ring base)
        float* stage = (float*)smem;
#pragma unroll
        for (int mi = 0; mi < 2; mi++) {
            const int rb = warp_m * 32 + mi * 16;
#pragma unroll
            for (int ni = 0; ni < 2; ni++) {
                const int cb = warp_n * 16 + ni * 8 + t4 * 2;
                *(float2*)&stage[(rb + g    ) * LDS_STAGE + cb] = make_float2(acc[mi][ni][0], acc[mi][ni][1]);
                *(float2*)&stage[(rb + g + 8) * LDS_STAGE + cb] = make_float2(acc[mi][ni][2], acc[mi][ni][3]);
            }
        }
        __syncthreads();

        // vectorized fused ADMM epilogue: each thread handles 2 groups of 8
        // consecutive columns (one swizzle group); R written as uint4.
        const int last = (it == ADMM_ITERS - 1);
        __nv_bfloat16* Rh = (it & 1) ? g_R0h : g_R1h;
        __nv_bfloat16* Rl = (it & 1) ? g_R0l : g_R1l;
#pragma unroll
        for (int gi = 0; gi < 2; gi++) {
            const int grp = tid + gi * 1024;      // 0..2047
            const int rr  = grp >> 4;             // row 0..127
            const int cc0 = (grp & 15) * 8;       // col group base
            float4 a0 = *(const float4*)&g_Atb[(size_t)(bm + rr) * NOUT + bn + cc0];
            float4 a1 = *(const float4*)&g_Atb[(size_t)(bm + rr) * NOUT + bn + cc0 + 4];
            const float* atb8 = &a0.x;            // a0,a1 contiguous on stack
            float atbv[8] = {a0.x, a0.y, a0.z, a0.w, a1.x, a1.y, a1.z, a1.w};
            (void)atb8;
            __nv_bfloat16 hv[8], lv[8];
            float vv[8];
#pragma unroll
            for (int j = 0; j < 8; j++) {
                const float x = stage[rr * LDS_STAGE + cc0 + j];
                const int uidx = rr * 128 + cc0 + j;
                const float u = Usm[uidx];
                const float tt = x + u;
                const float at = fabsf(tt) - LAMBD;
                const float v = at > 0.f ? copysignf(at, tt) : 0.f;
                const float un = tt - v;
                Usm[uidx] = un;
                vv[j] = v;
                const float rn = atbv[j] + v - un;
                const __nv_bfloat16 h = __float2bfloat16(rn);
                hv[j] = h;
                lv[j] = __float2bfloat16(rn - __bfloat162float(h));
            }
            if (last) {
                float* Vp = &V[(size_t)(bm + rr) * NOUT + bn + cc0];
                *(float4*)Vp       = make_float4(vv[0], vv[1], vv[2], vv[3]);
                *(float4*)(Vp + 4) = make_float4(vv[4], vv[5], vv[6], vv[7]);
            } else {
                const int kc = cc0 & 63;
                const int off = (mt16 + (blockIdx.x * 2 + (cc0 >> 6))) * 8192
                              + rr * 64 + (((kc >> 3) ^ (rr & 7)) * 8);
                *(uint4*)&Rh[off] = *(const uint4*)hv;
                *(uint4*)&Rl[off] = *(const uint4*)lv;
            }
        }

        // arrive on the inter-CTA barrier (wait happens at top of next iteration)
        if (!last) {
            __threadfence();
            __syncthreads();
            if (tid == 0) atomicAdd(&g_sync, 1);
        }
        __syncthreads();   // all threads past epilogue before next iter's mbar reinit
    }
}

// ---------------- launch ----------------
extern "C" void kernel_launch(void* const* d_in, const int* in_sizes, int n_in,
                              void* d_out, int out_size) {
    const float* x      = (const float*)d_in[0];
    const float* weight = (const float*)d_in[1];
    if (n_in >= 2 && in_sizes[0] == NOUT * NIN && in_sizes[1] == BATCH * NIN) {
        const float* t = x; x = weight; weight = t;
    }
    float* out = (float*)d_out;

    float *w, *wT, *S, *Xa, *Xb, *Y, *T, *Minv, *Atb, *pv0;
    cudaGetSymbolAddress((void**)&w,    g_w);
    cudaGetSymbolAddress((void**)&wT,   g_wT);
    cudaGetSymbolAddress((void**)&S,    g_S);
    cudaGetSymbolAddress((void**)&Xa,   g_Xa);
    cudaGetSymbolAddress((void**)&Xb,   g_Xb);
    cudaGetSymbolAddress((void**)&Y,    g_Yn);
    cudaGetSymbolAddress((void**)&T,    g_T);
    cudaGetSymbolAddress((void**)&Minv, g_Minv);
    cudaGetSymbolAddress((void**)&Atb,  g_Atb);
    cudaGetSymbolAddress((void**)&pv0,  g_pv0);

    cudaFuncSetAttribute(admm_persistent_kernel,
                         cudaFuncAttributeMaxDynamicSharedMemorySize, SM_TOT);

    // 1-2. normalize + transpose
    norm_rows_kernel<<<NOUT, 256>>>(weight);
    transpose_kernel<<<dim3(NIN / 32, NOUT / 32), dim3(32, 8)>>>();
    // 3. S = I + w^T w
    gemm_k<64, 64, 4, 4, EPI_ADD_EYE, 0><<<dim3(NIN / 64, NIN / 64), 256>>>(
        wT, wT, S, NIN, NIN, NOUT);
    // 4. power iteration -> alpha = 2/(1 + 1.2*lambda_hat)
    power_v0_kernel<<<1, NIN>>>();
    power_mv_kernel<<<NIN, 128>>>(pv0, Xa);
    power_mv_kernel<<<NIN, 128>>>(Xa, Xb);
    power_mv_kernel<<<NIN, 128>>>(Xb, Y);
    alpha_kernel<<<1, NIN>>>(Xb, Y);
    // 5. X0 = alpha * I
    init_x0_kernel<<<(NIN * NIN + 255) / 256, 256>>>();
    // 6. Newton-Schulz: X <- X (2I - S X)
    float* Xc = Xa; float* Xn = Xb;
    for (int i = 0; i < NEWTON_ITERS; i++) {
        gemm_k<64, 64, 4, 4, EPI_2EYE_MINUS, 1><<<dim3(NIN / 64, NIN / 64), 256>>>(
            S, Xc, Y, NIN, NIN, NIN);
        gemm_k<64, 64, 4, 4, EPI_PLAIN, 1><<<dim3(NIN / 64, NIN / 64), 256>>>(
            Xc, Y, Xn, NIN, NIN, NIN);
        float* tmp = Xc; Xc = Xn; Xn = tmp;
    }
    // 7. T = w @ Sinv
    gemm_k<64, 64, 4, 4, EPI_PLAIN, 1><<<dim3(NIN / 64, NOUT / 64), 256>>>(
        w, Xc, T, NOUT, NIN, NIN);
    // 8. Minv = I - T @ w^T
    gemm_k<64, 64, 4, 4, EPI_EYE_MINUS, 0><<<dim3(NOUT / 64, NOUT / 64), 256>>>(
        T, w, Minv, NOUT, NOUT, NIN);
    // 8b. split Minv -> packed bf16 hi/lo tile blocks
    split_minv_kernel<<<(NOUT * NOUT) / 256, 256>>>();
    // 9. Atb = x @ w^T
    gemm_k<128, 128, 8, 8, EPI_PLAIN, 0><<<dim3(NOUT / 128, BATCH / 128), 256>>>(
        x, w, Atb, BATCH, NOUT, NIN);
    // 10. R0 = packed split(Atb); reset barrier counter
    init_state_kernel<<<(BATCH * NOUT) / 256, 256>>>();
    // 11. persistent ADMM: ONE launch runs all 100 iterations
    admm_persistent_kernel<<<dim3(NOUT / 128, BATCH / 128), 1024, SM_TOT>>>(out);
    // 12. decoded = encoded @ w
    if (out_size >= BATCH * (NOUT + NIN)) {
        gemm_k<128, 128, 8, 8, EPI_PLAIN, 1><<<dim3(NIN / 128, BATCH / 128), 256>>>(
            out, w, out + (size_t)BATCH * NOUT, BATCH, NIN, NOUT);
    }
}

// round 16
// speedup vs baseline: 1.0612x; 1.0612x over previous
#include <cuda_runtime.h>
#include <cuda_bf16.h>
#include <math.h>
#include <stdint.h>

#define BATCH 2048
#define NIN   512
#define NOUT  1024
#define LAMBD 0.2f
#define ADMM_ITERS 100
#define NEWTON_ITERS 6
#define NCTAS 128

// ---------------- scratch (static __device__ globals: allocation-free) ----------------
__device__ __align__(16) float g_w   [NOUT*NIN];
__device__ __align__(16) float g_wT  [NIN*NOUT];
__device__ __align__(16) float g_S   [NIN*NIN];
__device__ __align__(16) float g_Xa  [NIN*NIN];
__device__ __align__(16) float g_Xb  [NIN*NIN];
__device__ __align__(16) float g_Yn  [NIN*NIN];
__device__ __align__(16) float g_T   [NOUT*NIN];
__device__ __align__(16) float g_Minv[NOUT*NOUT];
__device__ __align__(16) float g_Atb [BATCH*NOUT];
// packed tile-major buffers: [tile][chunk] blocks of 128x64 bf16 (16KB), swizzle baked in
__device__ __align__(16) __nv_bfloat16 g_Mh [NOUT*NOUT];
__device__ __align__(16) __nv_bfloat16 g_Ml [NOUT*NOUT];
__device__ __align__(16) __nv_bfloat16 g_R0h[BATCH*NOUT];
__device__ __align__(16) __nv_bfloat16 g_R0l[BATCH*NOUT];
__device__ __align__(16) __nv_bfloat16 g_R1h[BATCH*NOUT];
__device__ __align__(16) __nv_bfloat16 g_R1l[BATCH*NOUT];
__device__ float g_pv0[NIN];
__device__ float g_alpha;
__device__ int   g_sync;

// ---------------- PTX helpers ----------------
__device__ __forceinline__ uint32_t smem_u32(const void* p) {
    uint32_t a;
    asm("{ .reg .u64 t; cvta.to.shared.u64 t, %1; cvt.u32.u64 %0, t; }" : "=r"(a) : "l"(p));
    return a;
}
__device__ __forceinline__ void cpbulk(uint32_t dst, const void* src, uint32_t bytes, uint32_t mbar) {
    asm volatile(
        "cp.async.bulk.shared::cta.global.mbarrier::complete_tx::bytes [%0], [%1], %2, [%3];"
        :: "r"(dst), "l"(src), "r"(bytes), "r"(mbar) : "memory");
}
#define FENCE_ASYNC()    asm volatile("fence.proxy.async.shared::cta;" ::: "memory")
#define MBAR_INIT(mb, c) asm volatile("mbarrier.init.shared.b64 [%0], %1;" :: "r"(mb), "r"(c) : "memory")
#define MBAR_INVAL(mb)   asm volatile("mbarrier.inval.shared.b64 [%0];" :: "r"(mb) : "memory")
#define MBAR_EXPECT_TX(mb, n) asm volatile("mbarrier.arrive.expect_tx.shared.b64 _, [%0], %1;" :: "r"(mb), "r"(n) : "memory")
#define MBAR_ARRIVE(mb) asm volatile("mbarrier.arrive.shared.b64 _, [%0];" :: "r"(mb) : "memory")
#define MBAR_WAIT(mb, ph) do {                                                  \
    uint32_t _m = (mb), _p = (ph), _d;                                          \
    asm volatile("{\n\t.reg .pred p;\n\t"                                       \
        "mbarrier.try_wait.parity.acquire.cta.shared::cta.b64 p, [%1], %2;\n\t" \
        "selp.b32 %0, 1, 0, p;\n\t}" : "=r"(_d) : "r"(_m), "r"(_p) : "memory"); \
    if (!_d) {                                                                  \
        asm volatile("{\n\t.reg .pred P1;\n\t"                                  \
            "WL_%=:\n\t"                                                        \
            "mbarrier.try_wait.parity.acquire.cta.shared::cta.b64 P1, [%0], %1, 0x989680;\n\t" \
            "@P1 bra.uni WD_%=;\n\t"                                            \
            "bra.uni WL_%=;\n\t"                                                \
            "WD_%=:\n\t}" :: "r"(_m), "r"(_p) : "memory");                      \
    }                                                                           \
} while (0)
__device__ __forceinline__ void ldsm4(uint32_t* r, uint32_t addr) {
    asm volatile("ldmatrix.sync.aligned.m8n8.x4.shared.b16 {%0,%1,%2,%3}, [%4];"
        : "=r"(r[0]), "=r"(r[1]), "=r"(r[2]), "=r"(r[3]) : "r"(addr));
}
__device__ __forceinline__ void mma_bf16(float* c, const uint32_t* a, const uint32_t* b) {
    asm volatile(
        "mma.sync.aligned.m16n8k16.row.col.f32.bf16.bf16.f32 "
        "{%0,%1,%2,%3}, {%4,%5,%6,%7}, {%8,%9}, {%0,%1,%2,%3};"
        : "+f"(c[0]), "+f"(c[1]), "+f"(c[2]), "+f"(c[3])
        : "r"(a[0]), "r"(a[1]), "r"(a[2]), "r"(a[3]), "r"(b[0]), "r"(b[1]));
}

// packed offset (elements): matrix [rows][1024], tile = 128 rows x 64 cols, swizzle baked
__device__ __forceinline__ int packed_off(int row, int col) {
    const int r = row & 127;
    return ((row >> 7) * 16 + (col >> 6)) * 8192
         + r * 64 + ((((col & 63) >> 3) ^ (r & 7)) * 8) + (col & 7);
}

// ---------------- small kernels ----------------
__global__ void norm_rows_kernel(const float* __restrict__ win) {
    const int row = blockIdx.x;
    __shared__ float red[256];
    float s = 0.f;
    for (int c = threadIdx.x; c < NIN; c += 256) {
        float v = win[row * NIN + c];
        s += v * v;
    }
    red[threadIdx.x] = s;
    __syncthreads();
    for (int st = 128; st > 0; st >>= 1) {
        if (threadIdx.x < st) red[threadIdx.x] += red[threadIdx.x + st];
        __syncthreads();
    }
    const float inv = 1.f / sqrtf(red[0]);
    for (int c = threadIdx.x; c < NIN; c += 256)
        g_w[row * NIN + c] = win[row * NIN + c] * inv;
}

__global__ void transpose_kernel() {
    __shared__ float t[32][33];
    const int bx = blockIdx.x * 32, by = blockIdx.y * 32;
    for (int j = 0; j < 32; j += 8)
        t[threadIdx.y + j][threadIdx.x] = g_w[(by + threadIdx.y + j) * NIN + bx + threadIdx.x];
    __syncthreads();
    for (int j = 0; j < 32; j += 8)
        g_wT[(bx + threadIdx.y + j) * NOUT + by + threadIdx.x] = t[threadIdx.x][threadIdx.y + j];
}

__global__ void power_v0_kernel() {
    const int i = threadIdx.x;
    g_pv0[i] = 1.0f + 0.1f * (float)(i % 7);
}

__global__ void power_mv_kernel(const float* __restrict__ x, float* __restrict__ y) {
    const int row = blockIdx.x;
    __shared__ float red[128];
    float s = 0.f;
    for (int c = threadIdx.x; c < NIN; c += 128) s += g_S[row * NIN + c] * x[c];
    red[threadIdx.x] = s;
    __syncthreads();
    for (int st = 64; st > 0; st >>= 1) {
        if (threadIdx.x < st) red[threadIdx.x] += red[threadIdx.x + st];
        __syncthreads();
    }
    if (threadIdx.x == 0) y[row] = red[0];
}

__global__ void alpha_kernel(const float* __restrict__ v2, const float* __restrict__ v3) {
    __shared__ float r2[512], r3[512];
    const int i = threadIdx.x;
    r2[i] = v2[i] * v2[i];
    r3[i] = v3[i] * v3[i];
    __syncthreads();
    for (int st = 256; st > 0; st >>= 1) {
        if (i < st) { r2[i] += r2[i + st]; r3[i] += r3[i + st]; }
        __syncthreads();
    }
    if (i == 0) g_alpha = 2.f / (1.f + 1.2f * sqrtf(r3[0] / r2[0]));
}

__global__ void init_x0_kernel() {
    const int i = blockIdx.x * blockDim.x + threadIdx.x;
    if (i < NIN * NIN) {
        int r = i / NIN, c = i % NIN;
        g_Xa[i] = (r == c) ? g_alpha : 0.f;
    }
}

__global__ void split_minv_kernel() {
    const int i = blockIdx.x * blockDim.x + threadIdx.x;
    const int n = i >> 10, k = i & 1023;
    float v = g_Minv[i];
    __nv_bfloat16 h = __float2bfloat16(v);
    const int off = packed_off(n, k);
    g_Mh[off] = h;
    g_Ml[off] = __float2bfloat16(v - __bfloat162float(h));
}

__global__ void init_state_kernel() {   // R0 = packed split(Atb); reset global barrier
    const int i = blockIdx.x * blockDim.x + threadIdx.x;
    const int m = i >> 10, k = i & 1023;
    float v = g_Atb[i];
    __nv_bfloat16 h = __float2bfloat16(v);
    const int off = packed_off(m, k);
    g_R0h[off] = h;
    g_R0l[off] = __float2bfloat16(v - __bfloat162float(h));
    if (i == 0) g_sync = 0;
}

// ---------------- SIMT GEMM (prologue) ----------------
enum { EPI_PLAIN = 0, EPI_ADD_EYE = 1, EPI_EYE_MINUS = 2, EPI_2EYE_MINUS = 3 };

template <int BM, int BN, int TM, int TN, int EPI, int TB>
__global__ __launch_bounds__((BM / TM) * (BN / TN))
void gemm_k(const float* __restrict__ A, const float* __restrict__ B,
            float* __restrict__ C, int M, int N, int K)
{
    constexpr int BK = 16;
    constexpr int THREADS = (BM / TM) * (BN / TN);
    __shared__ float As[BK][BM];
    __shared__ float Bs[BK][BN];
    const int bm = blockIdx.y * BM, bn = blockIdx.x * BN;
    const int tid = threadIdx.x;
    const int tr = (tid / (BN / TN)) * TM;
    const int tc = (tid % (BN / TN)) * TN;

    float acc[TM][TN];
#pragma unroll
    for (int i = 0; i < TM; i++)
#pragma unroll
        for (int j = 0; j < TN; j++) acc[i][j] = 0.f;

    const float* Ap = A + (size_t)bm * K;
    constexpr int SLOTS_A = BM * (BK / 4);

    for (int k0 = 0; k0 < K; k0 += BK) {
        for (int s = tid; s < SLOTS_A; s += THREADS) {
            int r = s / (BK / 4), lc = (s % (BK / 4)) * 4;
            float4 v = *(const float4*)(Ap + (size_t)r * K + k0 + lc);
            As[lc + 0][r] = v.x; As[lc + 1][r] = v.y;
            As[lc + 2][r] = v.z; As[lc + 3][r] = v.w;
        }
        if (TB == 0) {
            constexpr int SLOTS_B = BN * (BK / 4);
            const float* Bp = B + (size_t)bn * K;
            for (int s = tid; s < SLOTS_B; s += THREADS) {
                int r = s / (BK / 4), lc = (s % (BK / 4)) * 4;
                float4 v = *(const float4*)(Bp + (size_t)r * K + k0 + lc);
                Bs[lc + 0][r] = v.x; Bs[lc + 1][r] = v.y;
                Bs[lc + 2][r] = v.z; Bs[lc + 3][r] = v.w;
            }
        } else {
            constexpr int SLOTS_B = BK * (BN / 4);
            for (int s = tid; s < SLOTS_B; s += THREADS) {
                int kk = s / (BN / 4), c4 = (s % (BN / 4)) * 4;
                float4 v = *(const float4*)(B + (size_t)(k0 + kk) * N + bn + c4);
                *(float4*)&Bs[kk][c4] = v;
            }
        }
        __syncthreads();
#pragma unroll
        for (int k = 0; k < BK; k++) {
            float a[TM], b[TN];
#pragma unroll
            for (int v = 0; v < TM; v += 4) *(float4*)&a[v] = *(const float4*)&As[k][tr + v];
#pragma unroll
            for (int v = 0; v < TN; v += 4) *(float4*)&b[v] = *(const float4*)&Bs[k][tc + v];
#pragma unroll
            for (int i = 0; i < TM; i++)
#pragma unroll
                for (int j = 0; j < TN; j++) acc[i][j] = fmaf(a[i], b[j], acc[i][j]);
        }
        __syncthreads();
    }

#pragma unroll
    for (int i = 0; i < TM; i++) {
        const int row = bm + tr + i;
#pragma unroll
        for (int j0 = 0; j0 < TN; j0 += 4) {
            const int col = bn + tc + j0;
            const size_t idx = (size_t)row * N + col;
            float r[4] = {acc[i][j0], acc[i][j0 + 1], acc[i][j0 + 2], acc[i][j0 + 3]};
            if (EPI == EPI_PLAIN) {
                *(float4*)(C + idx) = make_float4(r[0], r[1], r[2], r[3]);
            } else {
                float o[4];
#pragma unroll
                for (int c = 0; c < 4; c++) {
                    float e = (row == col + c) ? 1.f : 0.f;
                    o[c] = (EPI == EPI_ADD_EYE)  ? (r[c] + e)
                         : (EPI == EPI_EYE_MINUS) ? (e - r[c])
                                                  : (2.f * e - r[c]);
                }
                *(float4*)(C + idx) = make_float4(o[0], o[1], o[2], o[3]);
            }
        }
    }
}

// ---------------- persistent ADMM (R14 verified design): one launch, 100 iterations ----------------
// Monolithic per-chunk fills (single full barrier), mbarrier inval+reinit each
// iteration, atomic-poll global barrier, proxy fence. Compute path = R9
// (rel_err canary ~6.886e-05).
#define KC     64
#define NCH    (NOUT / KC)              // 16
#define TILE_B (128 * 64 * 2)           // 16384 bytes
#define STG_B  (4 * TILE_B)             // 65536 per stage
#define NSTAGE 2
#define SM_U    (NSTAGE * STG_B)        // 131072
#define SM_MBAR (SM_U + 65536)          // 196608
#define SM_TOT  (SM_MBAR + 64)          // 196672
#define LDS_STAGE 132                   // fp32 epilogue stage row stride (67584 <= 131072 ring)

__global__ __launch_bounds__(1024, 1)
void admm_persistent_kernel(float* __restrict__ V)
{
    extern __shared__ char smem[];
    const uint32_t sb = smem_u32(smem);
    const int tid = threadIdx.x;
    const int wid = tid >> 5, lane = tid & 31;
    const int g = lane >> 2, t4 = lane & 3;
    const int warp_m = wid & 3;
    const int warp_n = wid >> 2;
    const int bm = blockIdx.y * 128, bn = blockIdx.x * 128;
    const int mt16 = blockIdx.y * 16, nt16 = blockIdx.x * 16;

    const int lq = lane >> 3, lr = lane & 7;
    const int a_row0 = warp_m * 32 + (lq & 1) * 8 + lr;
    const int a_kq   = lq >> 1;
    const int b_row0 = warp_n * 16 + (lq >> 1) * 8 + lr;
    const int b_kq   = lq & 1;

    const uint32_t full_mb  = sb + SM_MBAR;        // 2 x 8 bytes
    const uint32_t empty_mb = sb + SM_MBAR + 16;   // 2 x 8 bytes
    float* Usm = (float*)(smem + SM_U);

#pragma unroll
    for (int i = 0; i < 16; i++) Usm[tid + i * 1024] = 0.f;
    __syncthreads();

    for (int it = 0; it < ADMM_ITERS; it++) {
        // (re)initialize pipeline barriers: every iteration starts at phase 0
        if (tid == 0) {
#pragma unroll
            for (int s = 0; s < NSTAGE; s++) {
                if (it > 0) { MBAR_INVAL(full_mb + s * 8); MBAR_INVAL(empty_mb + s * 8); }
                MBAR_INIT(full_mb  + s * 8, 1);
                MBAR_INIT(empty_mb + s * 8, 32);
            }
        }
        FENCE_ASYNC();     // order prior generic smem stores before async bulk writes
        __syncthreads();

        auto fill = [&](int ch) {
            const __nv_bfloat16* Ah = (it & 1) ? g_R1h : g_R0h;
            const __nv_bfloat16* Al = (it & 1) ? g_R1l : g_R0l;
            const int s = ch & 1;
            const uint32_t mb = full_mb + s * 8;
            MBAR_EXPECT_TX(mb, (uint32_t)STG_B);
            const uint32_t base = sb + s * STG_B;
            cpbulk(base,              Ah   + (size_t)(mt16 + ch) * 8192, TILE_B, mb);
            cpbulk(base + TILE_B,     Al   + (size_t)(mt16 + ch) * 8192, TILE_B, mb);
            cpbulk(base + 2 * TILE_B, g_Mh + (size_t)(nt16 + ch) * 8192, TILE_B, mb);
            cpbulk(base + 3 * TILE_B, g_Ml + (size_t)(nt16 + ch) * 8192, TILE_B, mb);
        };

        float acc[2][2][4];
#pragma unroll
        for (int i = 0; i < 2; i++)
#pragma unroll
            for (int j = 0; j < 2; j++)
#pragma unroll
                for (int c = 0; c < 4; c++) acc[i][j][c] = 0.f;

        if (tid == 0) { fill(0); fill(1); }

        for (int ch = 0; ch < NCH; ch++) {
            const int s = ch & 1;
            MBAR_WAIT(full_mb + s * 8, (ch >> 1) & 1);

            const uint32_t tAh = sb + s * STG_B;
            const uint32_t tAl = tAh + TILE_B;
            const uint32_t tBh = tAh + 2 * TILE_B;
            const uint32_t tBl = tAh + 3 * TILE_B;

#pragma unroll
            for (int ks = 0; ks < KC / 16; ks++) {
                const int kb8 = ks * 2;
                uint32_t ah[2][4], al[2][4], bh[4], bl[4];
#pragma unroll
                for (int mi = 0; mi < 2; mi++) {
                    const int row = a_row0 + mi * 16;
                    const uint32_t off = row * 128 + (((kb8 + a_kq) ^ (row & 7)) * 16);
                    ldsm4(ah[mi], tAh + off);
                    ldsm4(al[mi], tAl + off);
                }
                {
                    const uint32_t off = b_row0 * 128 + (((kb8 + b_kq) ^ (b_row0 & 7)) * 16);
                    ldsm4(bh, tBh + off);
                    ldsm4(bl, tBl + off);
                }
                if (ks == 3 && lane == 0 && ch < NCH - 2) MBAR_ARRIVE(empty_mb + s * 8);
                // product-outermost: per-acc order hh, hl, lh (canary order)
#pragma unroll
                for (int mi = 0; mi < 2; mi++) {
                    mma_bf16(acc[mi][0], ah[mi], bh);
                    mma_bf16(acc[mi][1], ah[mi], bh + 2);
                }
#pragma unroll
                for (int mi = 0; mi < 2; mi++) {
                    mma_bf16(acc[mi][0], ah[mi], bl);
                    mma_bf16(acc[mi][1], ah[mi], bl + 2);
                }
#pragma unroll
                for (int mi = 0; mi < 2; mi++) {
                    mma_bf16(acc[mi][0], al[mi], bh);
                    mma_bf16(acc[mi][1], al[mi], bh + 2);
                }
            }
            if (tid == 0 && ch + 2 < NCH) {
                MBAR_WAIT(empty_mb + s * 8, (ch >> 1) & 1);   // per-iter phase from 0
                fill(ch + 2);
            }
        }

        __syncthreads();   // mainloop done; ring smem reusable for staging

        // stage accumulators -> smem (fp32, stride LDS_STAGE at ring base)
        float* stage = (float*)smem;
#pragma unroll
        for (int mi = 0; mi < 2; mi++) {
            const int rb = warp_m * 32 + mi * 16;
#pragma unroll
            for (int ni = 0; ni < 2; ni++) {
                const int cb = warp_n * 16 + ni * 8 + t4 * 2;
                *(float2*)&stage[(rb + g    ) * LDS_STAGE + cb] = make_float2(acc[mi][ni][0], acc[mi][ni][1]);
                *(float2*)&stage[(rb + g + 8) * LDS_STAGE + cb] = make_float2(acc[mi][ni][2], acc[mi][ni][3]);
            }
        }
        __syncthreads();

        // fused ADMM elementwise; U in SMEM; R written packed (skip on last iter)
        const int last = (it == ADMM_ITERS - 1);
        __nv_bfloat16* Rh = (it & 1) ? g_R0h : g_R1h;
        __nv_bfloat16* Rl = (it & 1) ? g_R0l : g_R1l;
#pragma unroll 4
        for (int i = 0; i < 16; i++) {
            const int idx = tid + i * 1024;
            const int rr = idx >> 7, cc = idx & 127;
            const float x = stage[rr * LDS_STAGE + cc];
            const float u = Usm[idx];
            const float tt = x + u;
            const float at = fabsf(tt) - LAMBD;
            const float v = at > 0.f ? copysignf(at, tt) : 0.f;
            const float un = tt - v;
            Usm[idx] = un;
            if (last) {
                V[(size_t)(bm + rr) * NOUT + bn + cc] = v;
            } else {
                const float rn = g_Atb[(size_t)(bm + rr) * NOUT + bn + cc] + v - un;
                const __nv_bfloat16 h = __float2bfloat16(rn);
                const int kc = cc & 63;
                const int off = (mt16 + (blockIdx.x * 2 + (cc >> 6))) * 8192
                              + rr * 64 + ((((kc >> 3)) ^ (rr & 7)) * 8) + (kc & 7);
                Rh[off] = h;
                Rl[off] = __float2bfloat16(rn - __bfloat162float(h));
            }
        }

        // inter-CTA barrier (skip after last iteration); poll via L2 atomic
        if (!last) {
            __threadfence();
            __syncthreads();
            if (tid == 0) {
                atomicAdd(&g_sync, 1);
                const int target = NCTAS * (it + 1);
                while (atomicAdd(&g_sync, 0) < target) { }
                __threadfence();
            }
            __syncthreads();
        }
    }
}

// ---------------- launch ----------------
extern "C" void kernel_launch(void* const* d_in, const int* in_sizes, int n_in,
                              void* d_out, int out_size) {
    const float* x      = (const float*)d_in[0];
    const float* weight = (const float*)d_in[1];
    if (n_in >= 2 && in_sizes[0] == NOUT * NIN && in_sizes[1] == BATCH * NIN) {
        const float* t = x; x = weight; weight = t;
    }
    float* out = (float*)d_out;

    float *w, *wT, *S, *Xa, *Xb, *Y, *T, *Minv, *Atb, *pv0;
    cudaGetSymbolAddress((void**)&w,    g_w);
    cudaGetSymbolAddress((void**)&wT,   g_wT);
    cudaGetSymbolAddress((void**)&S,    g_S);
    cudaGetSymbolAddress((void**)&Xa,   g_Xa);
    cudaGetSymbolAddress((void**)&Xb,   g_Xb);
    cudaGetSymbolAddress((void**)&Y,    g_Yn);
    cudaGetSymbolAddress((void**)&T,    g_T);
    cudaGetSymbolAddress((void**)&Minv, g_Minv);
    cudaGetSymbolAddress((void**)&Atb,  g_Atb);
    cudaGetSymbolAddress((void**)&pv0,  g_pv0);

    cudaFuncSetAttribute(admm_persistent_kernel,
                         cudaFuncAttributeMaxDynamicSharedMemorySize, SM_TOT);

    // 1-2. normalize + transpose
    norm_rows_kernel<<<NOUT, 256>>>(weight);
    transpose_kernel<<<dim3(NIN / 32, NOUT / 32), dim3(32, 8)>>>();
    // 3. S = I + w^T w
    gemm_k<64, 64, 4, 4, EPI_ADD_EYE, 0><<<dim3(NIN / 64, NIN / 64), 256>>>(
        wT, wT, S, NIN, NIN, NOUT);
    // 4. power iteration -> alpha = 2/(1 + 1.2*lambda_hat)
    power_v0_kernel<<<1, NIN>>>();
    power_mv_kernel<<<NIN, 128>>>(pv0, Xa);
    power_mv_kernel<<<NIN, 128>>>(Xa, Xb);
    power_mv_kernel<<<NIN, 128>>>(Xb, Y);
    alpha_kernel<<<1, NIN>>>(Xb, Y);
    // 5. X0 = alpha * I
    init_x0_kernel<<<(NIN * NIN + 255) / 256, 256>>>();
    // 6. Newton-Schulz: X <- X (2I - S X); residual 0.783^(2^6) ~ 1.6e-7 << bf16 noise
    float* Xc = Xa; float* Xn = Xb;
    for (int i = 0; i < NEWTON_ITERS; i++) {
        gemm_k<64, 64, 4, 4, EPI_2EYE_MINUS, 1><<<dim3(NIN / 64, NIN / 64), 256>>>(
            S, Xc, Y, NIN, NIN, NIN);
        gemm_k<64, 64, 4, 4, EPI_PLAIN, 1><<<dim3(NIN / 64, NIN / 64), 256>>>(
            Xc, Y, Xn, NIN, NIN, NIN);
        float* tmp = Xc; Xc = Xn; Xn = tmp;
    }
    // 7. T = w @ Sinv
    gemm_k<64, 64, 4, 4, EPI_PLAIN, 1><<<dim3(NIN / 64, NOUT / 64), 256>>>(
        w, Xc, T, NOUT, NIN, NIN);
    // 8. Minv = I - T @ w^T
    gemm_k<64, 64, 4, 4, EPI_EYE_MINUS, 0><<<dim3(NOUT / 64, NOUT / 64), 256>>>(
        T, w, Minv, NOUT, NOUT, NIN);
    // 8b. split Minv -> packed bf16 hi/lo tile blocks
    split_minv_kernel<<<(NOUT * NOUT) / 256, 256>>>();
    // 9. Atb = x @ w^T
    gemm_k<128, 128, 8, 8, EPI_PLAIN, 0><<<dim3(NOUT / 128, BATCH / 128), 256>>>(
        x, w, Atb, BATCH, NOUT, NIN);
    // 10. R0 = packed split(Atb); reset barrier counter
    init_state_kernel<<<(BATCH * NOUT) / 256, 256>>>();
    // 11. persistent ADMM: ONE launch runs all 100 iterations
    admm_persistent_kernel<<<dim3(NOUT / 128, BATCH / 128), 1024, SM_TOT>>>(out);
    // 12. decoded = encoded @ w
    if (out_size >= BATCH * (NOUT + NIN)) {
        gemm_k<128, 128, 8, 8, EPI_PLAIN, 1><<<dim3(NIN / 128, BATCH / 128), 256>>>(
            out, w, out + (size_t)BATCH * NOUT, BATCH, NIN, NOUT);
    }
}

// round 17
// speedup vs baseline: 1.0852x; 1.0226x over previous
#include <cuda_runtime.h>
#include <cuda_bf16.h>
#include <math.h>
#include <stdint.h>

#define BATCH 2048
#define NIN   512
#define NOUT  1024
#define LAMBD 0.2f
#define ADMM_ITERS 100
#define NEWTON_ITERS 6
#define NCTAS 128

// ---------------- scratch (static __device__ globals: allocation-free) ----------------
__device__ __align__(16) float g_w   [NOUT*NIN];
__device__ __align__(16) float g_wT  [NIN*NOUT];
__device__ __align__(16) float g_S   [NIN*NIN];
__device__ __align__(16) float g_Xa  [NIN*NIN];
__device__ __align__(16) float g_Xb  [NIN*NIN];
__device__ __align__(16) float g_Yn  [NIN*NIN];
__device__ __align__(16) float g_T   [NOUT*NIN];
__device__ __align__(16) float g_Minv[NOUT*NOUT];
__device__ __align__(16) float g_Atb [BATCH*NOUT];
// packed tile-major buffers: [tile][chunk] blocks of 128x64 bf16 (16KB), swizzle baked in
__device__ __align__(16) __nv_bfloat16 g_Mh [NOUT*NOUT];
__device__ __align__(16) __nv_bfloat16 g_Ml [NOUT*NOUT];
__device__ __align__(16) __nv_bfloat16 g_R0h[BATCH*NOUT];
__device__ __align__(16) __nv_bfloat16 g_R0l[BATCH*NOUT];
__device__ __align__(16) __nv_bfloat16 g_R1h[BATCH*NOUT];
__device__ __align__(16) __nv_bfloat16 g_R1l[BATCH*NOUT];
__device__ float g_pv0[NIN];
__device__ float g_alpha;
__device__ int   g_sync;

// ---------------- PTX helpers ----------------
__device__ __forceinline__ uint32_t smem_u32(const void* p) {
    uint32_t a;
    asm("{ .reg .u64 t; cvta.to.shared.u64 t, %1; cvt.u32.u64 %0, t; }" : "=r"(a) : "l"(p));
    return a;
}
__device__ __forceinline__ void cpbulk(uint32_t dst, const void* src, uint32_t bytes, uint32_t mbar) {
    asm volatile(
        "cp.async.bulk.shared::cta.global.mbarrier::complete_tx::bytes [%0], [%1], %2, [%3];"
        :: "r"(dst), "l"(src), "r"(bytes), "r"(mbar) : "memory");
}
#define FENCE_ASYNC()    asm volatile("fence.proxy.async.shared::cta;" ::: "memory")
#define MBAR_INIT(mb, c) asm volatile("mbarrier.init.shared.b64 [%0], %1;" :: "r"(mb), "r"(c) : "memory")
#define MBAR_INVAL(mb)   asm volatile("mbarrier.inval.shared.b64 [%0];" :: "r"(mb) : "memory")
#define MBAR_EXPECT_TX(mb, n) asm volatile("mbarrier.arrive.expect_tx.shared.b64 _, [%0], %1;" :: "r"(mb), "r"(n) : "memory")
#define MBAR_ARRIVE(mb) asm volatile("mbarrier.arrive.shared.b64 _, [%0];" :: "r"(mb) : "memory")
#define MBAR_WAIT(mb, ph) do {                                                  \
    uint32_t _m = (mb), _p = (ph), _d;                                          \
    asm volatile("{\n\t.reg .pred p;\n\t"                                       \
        "mbarrier.try_wait.parity.acquire.cta.shared::cta.b64 p, [%1], %2;\n\t" \
        "selp.b32 %0, 1, 0, p;\n\t}" : "=r"(_d) : "r"(_m), "r"(_p) : "memory"); \
    if (!_d) {                                                                  \
        asm volatile("{\n\t.reg .pred P1;\n\t"                                  \
            "WL_%=:\n\t"                                                        \
            "mbarrier.try_wait.parity.acquire.cta.shared::cta.b64 P1, [%0], %1, 0x989680;\n\t" \
            "@P1 bra.uni WD_%=;\n\t"                                            \
            "bra.uni WL_%=;\n\t"                                                \
            "WD_%=:\n\t}" :: "r"(_m), "r"(_p) : "memory");                      \
    }                                                                           \
} while (0)
__device__ __forceinline__ void ldsm4(uint32_t* r, uint32_t addr) {
    asm volatile("ldmatrix.sync.aligned.m8n8.x4.shared.b16 {%0,%1,%2,%3}, [%4];"
        : "=r"(r[0]), "=r"(r[1]), "=r"(r[2]), "=r"(r[3]) : "r"(addr));
}
__device__ __forceinline__ void mma_bf16(float* c, const uint32_t* a, const uint32_t* b) {
    asm volatile(
        "mma.sync.aligned.m16n8k16.row.col.f32.bf16.bf16.f32 "
        "{%0,%1,%2,%3}, {%4,%5,%6,%7}, {%8,%9}, {%0,%1,%2,%3};"
        : "+f"(c[0]), "+f"(c[1]), "+f"(c[2]), "+f"(c[3])
        : "r"(a[0]), "r"(a[1]), "r"(a[2]), "r"(a[3]), "r"(b[0]), "r"(b[1]));
}

// packed offset (elements): matrix [rows][1024], tile = 128 rows x 64 cols, swizzle baked
__device__ __forceinline__ int packed_off(int row, int col) {
    const int r = row & 127;
    return ((row >> 7) * 16 + (col >> 6)) * 8192
         + r * 64 + ((((col & 63) >> 3) ^ (r & 7)) * 8) + (col & 7);
}

// ---------------- small kernels ----------------
__global__ void norm_rows_kernel(const float* __restrict__ win) {
    const int row = blockIdx.x;
    __shared__ float red[256];
    float s = 0.f;
    for (int c = threadIdx.x; c < NIN; c += 256) {
        float v = win[row * NIN + c];
        s += v * v;
    }
    red[threadIdx.x] = s;
    __syncthreads();
    for (int st = 128; st > 0; st >>= 1) {
        if (threadIdx.x < st) red[threadIdx.x] += red[threadIdx.x + st];
        __syncthreads();
    }
    const float inv = 1.f / sqrtf(red[0]);
    for (int c = threadIdx.x; c < NIN; c += 256)
        g_w[row * NIN + c] = win[row * NIN + c] * inv;
}

__global__ void transpose_kernel() {
    __shared__ float t[32][33];
    const int bx = blockIdx.x * 32, by = blockIdx.y * 32;
    for (int j = 0; j < 32; j += 8)
        t[threadIdx.y + j][threadIdx.x] = g_w[(by + threadIdx.y + j) * NIN + bx + threadIdx.x];
    __syncthreads();
    for (int j = 0; j < 32; j += 8)
        g_wT[(bx + threadIdx.y + j) * NOUT + by + threadIdx.x] = t[threadIdx.x][threadIdx.y + j];
}

__global__ void power_v0_kernel() {
    const int i = threadIdx.x;
    g_pv0[i] = 1.0f + 0.1f * (float)(i % 7);
}

__global__ void power_mv_kernel(const float* __restrict__ x, float* __restrict__ y) {
    const int row = blockIdx.x;
    __shared__ float red[128];
    float s = 0.f;
    for (int c = threadIdx.x; c < NIN; c += 128) s += g_S[row * NIN + c] * x[c];
    red[threadIdx.x] = s;
    __syncthreads();
    for (int st = 64; st > 0; st >>= 1) {
        if (threadIdx.x < st) red[threadIdx.x] += red[threadIdx.x + st];
        __syncthreads();
    }
    if (threadIdx.x == 0) y[row] = red[0];
}

__global__ void alpha_kernel(const float* __restrict__ v2, const float* __restrict__ v3) {
    __shared__ float r2[512], r3[512];
    const int i = threadIdx.x;
    r2[i] = v2[i] * v2[i];
    r3[i] = v3[i] * v3[i];
    __syncthreads();
    for (int st = 256; st > 0; st >>= 1) {
        if (i < st) { r2[i] += r2[i + st]; r3[i] += r3[i + st]; }
        __syncthreads();
    }
    if (i == 0) g_alpha = 2.f / (1.f + 1.2f * sqrtf(r3[0] / r2[0]));
}

__global__ void init_x0_kernel() {
    const int i = blockIdx.x * blockDim.x + threadIdx.x;
    if (i < NIN * NIN) {
        int r = i / NIN, c = i % NIN;
        g_Xa[i] = (r == c) ? g_alpha : 0.f;
    }
}

__global__ void split_minv_kernel() {
    const int i = blockIdx.x * blockDim.x + threadIdx.x;
    const int n = i >> 10, k = i & 1023;
    float v = g_Minv[i];
    __nv_bfloat16 h = __float2bfloat16(v);
    const int off = packed_off(n, k);
    g_Mh[off] = h;
    g_Ml[off] = __float2bfloat16(v - __bfloat162float(h));
}

__global__ void init_state_kernel() {   // R0 = packed split(Atb); reset global barrier
    const int i = blockIdx.x * blockDim.x + threadIdx.x;
    const int m = i >> 10, k = i & 1023;
    float v = g_Atb[i];
    __nv_bfloat16 h = __float2bfloat16(v);
    const int off = packed_off(m, k);
    g_R0h[off] = h;
    g_R0l[off] = __float2bfloat16(v - __bfloat162float(h));
    if (i == 0) g_sync = 0;
}

// ---------------- SIMT GEMM (prologue / epilogue) ----------------
enum { EPI_PLAIN = 0, EPI_ADD_EYE = 1, EPI_EYE_MINUS = 2, EPI_2EYE_MINUS = 3 };

template <int BM, int BN, int TM, int TN, int EPI, int TB>
__global__ __launch_bounds__((BM / TM) * (BN / TN))
void gemm_k(const float* __restrict__ A, const float* __restrict__ B,
            float* __restrict__ C, int M, int N, int K)
{
    constexpr int BK = 16;
    constexpr int THREADS = (BM / TM) * (BN / TN);
    __shared__ float As[BK][BM];
    __shared__ float Bs[BK][BN];
    const int bm = blockIdx.y * BM, bn = blockIdx.x * BN;
    const int tid = threadIdx.x;
    const int tr = (tid / (BN / TN)) * TM;
    const int tc = (tid % (BN / TN)) * TN;

    float acc[TM][TN];
#pragma unroll
    for (int i = 0; i < TM; i++)
#pragma unroll
        for (int j = 0; j < TN; j++) acc[i][j] = 0.f;

    const float* Ap = A + (size_t)bm * K;
    constexpr int SLOTS_A = BM * (BK / 4);

    for (int k0 = 0; k0 < K; k0 += BK) {
        for (int s = tid; s < SLOTS_A; s += THREADS) {
            int r = s / (BK / 4), lc = (s % (BK / 4)) * 4;
            float4 v = *(const float4*)(Ap + (size_t)r * K + k0 + lc);
            As[lc + 0][r] = v.x; As[lc + 1][r] = v.y;
            As[lc + 2][r] = v.z; As[lc + 3][r] = v.w;
        }
        if (TB == 0) {
            constexpr int SLOTS_B = BN * (BK / 4);
            const float* Bp = B + (size_t)bn * K;
            for (int s = tid; s < SLOTS_B; s += THREADS) {
                int r = s / (BK / 4), lc = (s % (BK / 4)) * 4;
                float4 v = *(const float4*)(Bp + (size_t)r * K + k0 + lc);
                Bs[lc + 0][r] = v.x; Bs[lc + 1][r] = v.y;
                Bs[lc + 2][r] = v.z; Bs[lc + 3][r] = v.w;
            }
        } else {
            constexpr int SLOTS_B = BK * (BN / 4);
            for (int s = tid; s < SLOTS_B; s += THREADS) {
                int kk = s / (BN / 4), c4 = (s % (BN / 4)) * 4;
                float4 v = *(const float4*)(B + (size_t)(k0 + kk) * N + bn + c4);
                *(float4*)&Bs[kk][c4] = v;
            }
        }
        __syncthreads();
#pragma unroll
        for (int k = 0; k < BK; k++) {
            float a[TM], b[TN];
#pragma unroll
            for (int v = 0; v < TM; v += 4) *(float4*)&a[v] = *(const float4*)&As[k][tr + v];
#pragma unroll
            for (int v = 0; v < TN; v += 4) *(float4*)&b[v] = *(const float4*)&Bs[k][tc + v];
#pragma unroll
            for (int i = 0; i < TM; i++)
#pragma unroll
                for (int j = 0; j < TN; j++) acc[i][j] = fmaf(a[i], b[j], acc[i][j]);
        }
        __syncthreads();
    }

#pragma unroll
    for (int i = 0; i < TM; i++) {
        const int row = bm + tr + i;
#pragma unroll
        for (int j0 = 0; j0 < TN; j0 += 4) {
            const int col = bn + tc + j0;
            const size_t idx = (size_t)row * N + col;
            float r[4] = {acc[i][j0], acc[i][j0 + 1], acc[i][j0 + 2], acc[i][j0 + 3]};
            if (EPI == EPI_PLAIN) {
                *(float4*)(C + idx) = make_float4(r[0], r[1], r[2], r[3]);
            } else {
                float o[4];
#pragma unroll
                for (int c = 0; c < 4; c++) {
                    float e = (row == col + c) ? 1.f : 0.f;
                    o[c] = (EPI == EPI_ADD_EYE)  ? (r[c] + e)
                         : (EPI == EPI_EYE_MINUS) ? (e - r[c])
                                                  : (2.f * e - r[c]);
                }
                *(float4*)(C + idx) = make_float4(o[0], o[1], o[2], o[3]);
            }
        }
    }
}

// ---------------- persistent ADMM (R14/R16 verified design): one launch, 100 iterations ----------------
// Monolithic per-chunk fills (single full barrier), mbarrier inval+reinit each
// iteration, atomic-poll global barrier, proxy fence. Compute path = R9
// (rel_err canary 1.595454e-04 with Newton-6).
#define KC     64
#define NCH    (NOUT / KC)              // 16
#define TILE_B (128 * 64 * 2)           // 16384 bytes
#define STG_B  (4 * TILE_B)             // 65536 per stage
#define NSTAGE 2
#define SM_U    (NSTAGE * STG_B)        // 131072
#define SM_MBAR (SM_U + 65536)          // 196608
#define SM_TOT  (SM_MBAR + 64)          // 196672
#define LDS_STAGE 132                   // fp32 epilogue stage row stride (67584 <= 131072 ring)

__global__ __launch_bounds__(1024, 1)
void admm_persistent_kernel(float* __restrict__ V)
{
    extern __shared__ char smem[];
    const uint32_t sb = smem_u32(smem);
    const int tid = threadIdx.x;
    const int wid = tid >> 5, lane = tid & 31;
    const int g = lane >> 2, t4 = lane & 3;
    const int warp_m = wid & 3;
    const int warp_n = wid >> 2;
    const int bm = blockIdx.y * 128, bn = blockIdx.x * 128;
    const int mt16 = blockIdx.y * 16, nt16 = blockIdx.x * 16;

    const int lq = lane >> 3, lr = lane & 7;
    const int a_row0 = warp_m * 32 + (lq & 1) * 8 + lr;
    const int a_kq   = lq >> 1;
    const int b_row0 = warp_n * 16 + (lq >> 1) * 8 + lr;
    const int b_kq   = lq & 1;

    const uint32_t full_mb  = sb + SM_MBAR;        // 2 x 8 bytes
    const uint32_t empty_mb = sb + SM_MBAR + 16;   // 2 x 8 bytes
    float* Usm = (float*)(smem + SM_U);

#pragma unroll
    for (int i = 0; i < 16; i++) Usm[tid + i * 1024] = 0.f;
    __syncthreads();

    for (int it = 0; it < ADMM_ITERS; it++) {
        // (re)initialize pipeline barriers: every iteration starts at phase 0
        if (tid == 0) {
#pragma unroll
            for (int s = 0; s < NSTAGE; s++) {
                if (it > 0) { MBAR_INVAL(full_mb + s * 8); MBAR_INVAL(empty_mb + s * 8); }
                MBAR_INIT(full_mb  + s * 8, 1);
                MBAR_INIT(empty_mb + s * 8, 32);
            }
        }
        FENCE_ASYNC();     // order prior generic smem stores before async bulk writes
        __syncthreads();

        auto fill = [&](int ch) {
            const __nv_bfloat16* Ah = (it & 1) ? g_R1h : g_R0h;
            const __nv_bfloat16* Al = (it & 1) ? g_R1l : g_R0l;
            const int s = ch & 1;
            const uint32_t mb = full_mb + s * 8;
            MBAR_EXPECT_TX(mb, (uint32_t)STG_B);
            const uint32_t base = sb + s * STG_B;
            cpbulk(base,              Ah   + (size_t)(mt16 + ch) * 8192, TILE_B, mb);
            cpbulk(base + TILE_B,     Al   + (size_t)(mt16 + ch) * 8192, TILE_B, mb);
            cpbulk(base + 2 * TILE_B, g_Mh + (size_t)(nt16 + ch) * 8192, TILE_B, mb);
            cpbulk(base + 3 * TILE_B, g_Ml + (size_t)(nt16 + ch) * 8192, TILE_B, mb);
        };

        float acc[2][2][4];
#pragma unroll
        for (int i = 0; i < 2; i++)
#pragma unroll
            for (int j = 0; j < 2; j++)
#pragma unroll
                for (int c = 0; c < 4; c++) acc[i][j][c] = 0.f;

        if (tid == 0) { fill(0); fill(1); }

        for (int ch = 0; ch < NCH; ch++) {
            const int s = ch & 1;
            MBAR_WAIT(full_mb + s * 8, (ch >> 1) & 1);

            const uint32_t tAh = sb + s * STG_B;
            const uint32_t tAl = tAh + TILE_B;
            const uint32_t tBh = tAh + 2 * TILE_B;
            const uint32_t tBl = tAh + 3 * TILE_B;

#pragma unroll
            for (int ks = 0; ks < KC / 16; ks++) {
                const int kb8 = ks * 2;
                uint32_t ah[2][4], al[2][4], bh[4], bl[4];
#pragma unroll
                for (int mi = 0; mi < 2; mi++) {
                    const int row = a_row0 + mi * 16;
                    const uint32_t off = row * 128 + (((kb8 + a_kq) ^ (row & 7)) * 16);
                    ldsm4(ah[mi], tAh + off);
                    ldsm4(al[mi], tAl + off);
                }
                {
                    const uint32_t off = b_row0 * 128 + (((kb8 + b_kq) ^ (b_row0 & 7)) * 16);
                    ldsm4(bh, tBh + off);
                    ldsm4(bl, tBl + off);
                }
                if (ks == 3 && lane == 0 && ch < NCH - 2) MBAR_ARRIVE(empty_mb + s * 8);
                // product-outermost: per-acc order hh, hl, lh (canary order)
#pragma unroll
                for (int mi = 0; mi < 2; mi++) {
                    mma_bf16(acc[mi][0], ah[mi], bh);
                    mma_bf16(acc[mi][1], ah[mi], bh + 2);
                }
#pragma unroll
                for (int mi = 0; mi < 2; mi++) {
                    mma_bf16(acc[mi][0], ah[mi], bl);
                    mma_bf16(acc[mi][1], ah[mi], bl + 2);
                }
#pragma unroll
                for (int mi = 0; mi < 2; mi++) {
                    mma_bf16(acc[mi][0], al[mi], bh);
                    mma_bf16(acc[mi][1], al[mi], bh + 2);
                }
            }
            if (tid == 0 && ch + 2 < NCH) {
                MBAR_WAIT(empty_mb + s * 8, (ch >> 1) & 1);   // per-iter phase from 0
                fill(ch + 2);
            }
        }

        __syncthreads();   // mainloop done; ring smem reusable for staging

        // stage accumulators -> smem (fp32, stride LDS_STAGE at ring base)
        float* stage = (float*)smem;
#pragma unroll
        for (int mi = 0; mi < 2; mi++) {
            const int rb = warp_m * 32 + mi * 16;
#pragma unroll
            for (int ni = 0; ni < 2; ni++) {
                const int cb = warp_n * 16 + ni * 8 + t4 * 2;
                *(float2*)&stage[(rb + g    ) * LDS_STAGE + cb] = make_float2(acc[mi][ni][0], acc[mi][ni][1]);
                *(float2*)&stage[(rb + g + 8) * LDS_STAGE + cb] = make_float2(acc[mi][ni][2], acc[mi][ni][3]);
            }
        }
        __syncthreads();

        // fused ADMM elementwise; U in SMEM; R written packed (skip on last iter)
        const int last = (it == ADMM_ITERS - 1);
        __nv_bfloat16* Rh = (it & 1) ? g_R0h : g_R1h;
        __nv_bfloat16* Rl = (it & 1) ? g_R0l : g_R1l;
#pragma unroll 4
        for (int i = 0; i < 16; i++) {
            const int idx = tid + i * 1024;
            const int rr = idx >> 7, cc = idx & 127;
            const float x = stage[rr * LDS_STAGE + cc];
            const float u = Usm[idx];
            const float tt = x + u;
            const float at = fabsf(tt) - LAMBD;
            const float v = at > 0.f ? copysignf(at, tt) : 0.f;
            const float un = tt - v;
            Usm[idx] = un;
            if (last) {
                V[(size_t)(bm + rr) * NOUT + bn + cc] = v;
            } else {
                const float rn = g_Atb[(size_t)(bm + rr) * NOUT + bn + cc] + v - un;
                const __nv_bfloat16 h = __float2bfloat16(rn);
                const int kc = cc & 63;
                const int off = (mt16 + (blockIdx.x * 2 + (cc >> 6))) * 8192
                              + rr * 64 + ((((kc >> 3)) ^ (rr & 7)) * 8) + (kc & 7);
                Rh[off] = h;
                Rl[off] = __float2bfloat16(rn - __bfloat162float(h));
            }
        }

        // inter-CTA barrier (skip after last iteration); poll via L2 atomic
        if (!last) {
            __threadfence();
            __syncthreads();
            if (tid == 0) {
                atomicAdd(&g_sync, 1);
                const int target = NCTAS * (it + 1);
                while (atomicAdd(&g_sync, 0) < target) { }
                __threadfence();
            }
            __syncthreads();
        }
    }
}

// ---------------- launch ----------------
extern "C" void kernel_launch(void* const* d_in, const int* in_sizes, int n_in,
                              void* d_out, int out_size) {
    const float* x      = (const float*)d_in[0];
    const float* weight = (const float*)d_in[1];
    if (n_in >= 2 && in_sizes[0] == NOUT * NIN && in_sizes[1] == BATCH * NIN) {
        const float* t = x; x = weight; weight = t;
    }
    float* out = (float*)d_out;

    float *w, *wT, *S, *Xa, *Xb, *Y, *T, *Minv, *Atb, *pv0;
    cudaGetSymbolAddress((void**)&w,    g_w);
    cudaGetSymbolAddress((void**)&wT,   g_wT);
    cudaGetSymbolAddress((void**)&S,    g_S);
    cudaGetSymbolAddress((void**)&Xa,   g_Xa);
    cudaGetSymbolAddress((void**)&Xb,   g_Xb);
    cudaGetSymbolAddress((void**)&Y,    g_Yn);
    cudaGetSymbolAddress((void**)&T,    g_T);
    cudaGetSymbolAddress((void**)&Minv, g_Minv);
    cudaGetSymbolAddress((void**)&Atb,  g_Atb);
    cudaGetSymbolAddress((void**)&pv0,  g_pv0);

    cudaFuncSetAttribute(admm_persistent_kernel,
                         cudaFuncAttributeMaxDynamicSharedMemorySize, SM_TOT);

    // 1-2. normalize + transpose
    norm_rows_kernel<<<NOUT, 256>>>(weight);
    transpose_kernel<<<dim3(NIN / 32, NOUT / 32), dim3(32, 8)>>>();
    // 3. S = I + w^T w
    gemm_k<64, 64, 4, 4, EPI_ADD_EYE, 0><<<dim3(NIN / 64, NIN / 64), 256>>>(
        wT, wT, S, NIN, NIN, NOUT);
    // 4. power iteration -> alpha = 2/(1 + 1.2*lambda_hat)
    power_v0_kernel<<<1, NIN>>>();
    power_mv_kernel<<<NIN, 128>>>(pv0, Xa);
    power_mv_kernel<<<NIN, 128>>>(Xa, Xb);
    power_mv_kernel<<<NIN, 128>>>(Xb, Y);
    alpha_kernel<<<1, NIN>>>(Xb, Y);
    // 5. X0 = alpha * I
    init_x0_kernel<<<(NIN * NIN + 255) / 256, 256>>>();
    // 6. Newton-Schulz: X <- X (2I - S X)
    float* Xc = Xa; float* Xn = Xb;
    for (int i = 0; i < NEWTON_ITERS; i++) {
        gemm_k<64, 64, 4, 4, EPI_2EYE_MINUS, 1><<<dim3(NIN / 64, NIN / 64), 256>>>(
            S, Xc, Y, NIN, NIN, NIN);
        gemm_k<64, 64, 4, 4, EPI_PLAIN, 1><<<dim3(NIN / 64, NIN / 64), 256>>>(
            Xc, Y, Xn, NIN, NIN, NIN);
        float* tmp = Xc; Xc = Xn; Xn = tmp;
    }
    // 7. T = w @ Sinv
    gemm_k<64, 64, 4, 4, EPI_PLAIN, 1><<<dim3(NIN / 64, NOUT / 64), 256>>>(
        w, Xc, T, NOUT, NIN, NIN);
    // 8. Minv = I - T @ w^T
    gemm_k<64, 64, 4, 4, EPI_EYE_MINUS, 0><<<dim3(NOUT / 64, NOUT / 64), 256>>>(
        T, w, Minv, NOUT, NOUT, NIN);
    // 8b. split Minv -> packed bf16 hi/lo tile blocks
    split_minv_kernel<<<(NOUT * NOUT) / 256, 256>>>();
    // 9. Atb = x @ w^T
    gemm_k<128, 128, 8, 8, EPI_PLAIN, 0><<<dim3(NOUT / 128, BATCH / 128), 256>>>(
        x, w, Atb, BATCH, NOUT, NIN);
    // 10. R0 = packed split(Atb); reset barrier counter
    init_state_kernel<<<(BATCH * NOUT) / 256, 256>>>();
    // 11. persistent ADMM: ONE launch runs all 100 iterations
    admm_persistent_kernel<<<dim3(NOUT / 128, BATCH / 128), 1024, SM_TOT>>>(out);
    // 12. decoded = encoded @ w (NN) — 128x64 tiles -> 128 CTAs (was 64);
    // per-element k-summation order unchanged -> bit-identical output
    gemm_k<128, 64, 8, 4, EPI_PLAIN, 1><<<dim3(NIN / 64, BATCH / 128), 256>>>(
        out, w, out + (size_t)BATCH * NOUT, BATCH, NIN, NOUT);
}